// round 6
// baseline (speedup 1.0000x reference)
#include <cuda_runtime.h>

#define BATCH 2
#define NH    8
#define S     512
#define D     64
#define NC    8
#define NB    4
#define BH    (BATCH*NH)

// Scratch (device globals: allocation rules forbid cudaMalloc)
__device__ float g_W1m[NC*NH*D*D];      // mixed W1_ [c][h][m][n]
__device__ float g_W2m[NC*NH*D*D];      // mixed W2_ [c][h][d][D]
__device__ float g_uq [NC*BH*S*D];      // q @ W1_[c]  : [c][bh][i][n]
__device__ float g_t  [NC*BH*S*D];      // v @ W2_[c]  : [c][bh][j][Dd]
__device__ float g_P  [BH*S*S];         // softmax probabilities [bh][i][j]

typedef unsigned long long u64;

// ---- f32x2 helpers ----
__device__ __forceinline__ u64 pk2f(float x, float y) {
    u64 r; asm("mov.b64 %0, {%1, %2};" : "=l"(r) : "f"(x), "f"(y)); return r;
}
__device__ __forceinline__ void fma2(u64& acc, u64 a, u64 b) {
    asm("fma.rn.f32x2 %0, %1, %2, %0;" : "+l"(acc) : "l"(a), "l"(b));
}
__device__ __forceinline__ float lo32(u64 v) {
    return __int_as_float((int)(unsigned)(v & 0xffffffffULL));
}
__device__ __forceinline__ float hi32(u64 v) {
    return __int_as_float((int)(unsigned)(v >> 32));
}

// ---- cp.async helpers ----
__device__ __forceinline__ void cpa16(unsigned dst_smem, const void* src) {
    asm volatile("cp.async.cg.shared.global [%0], [%1], 16;"
                 :: "r"(dst_smem), "l"(src) : "memory");
}
__device__ __forceinline__ void cpa_commit() {
    asm volatile("cp.async.commit_group;" ::: "memory");
}
__device__ __forceinline__ void cpa_wait0() {
    asm volatile("cp.async.wait_group 0;" ::: "memory");
}

// ---------------------------------------------------------------------------
// K1: mix the B bases into C class matrices; also zero d_out (poisoned).
// ---------------------------------------------------------------------------
__global__ void k_mixw(const float* __restrict__ W1, const float* __restrict__ A1,
                       const float* __restrict__ W2, const float* __restrict__ A2,
                       float4* __restrict__ outz)
{
    for (int i = blockIdx.x*256 + threadIdx.x; i < BH*S*D/4; i += 128*256)
        outz[i] = make_float4(0.f,0.f,0.f,0.f);

    int arr = blockIdx.x >> 6;
    int c   = (blockIdx.x >> 3) & 7;
    int hh  = blockIdx.x & 7;
    const float* W = arr ? W2 : W1;
    const float* A = arr ? A2 : A1;
    float* Wo = (arr ? g_W2m : g_W1m) + (c*NH + hh)*D*D;

    __shared__ float wsm[NB];
    if (threadIdx.x == 0) {
        float av[NB]; float mx = -1e30f;
        #pragma unroll
        for (int bb = 0; bb < NB; bb++) { av[bb] = A[(c*NB+bb)*NH + hh]; mx = fmaxf(mx, av[bb]); }
        float ssum = 0.f;
        #pragma unroll
        for (int bb = 0; bb < NB; bb++) { av[bb] = __expf(av[bb]-mx); ssum += av[bb]; }
        #pragma unroll
        for (int bb = 0; bb < NB; bb++) wsm[bb] = av[bb]/ssum;
    }
    __syncthreads();
    float w0 = wsm[0], w1 = wsm[1], w2 = wsm[2], w3 = wsm[3];
    const float* p0 = W + (0*NH+hh)*D*D;
    const float* p1 = W + (1*NH+hh)*D*D;
    const float* p2 = W + (2*NH+hh)*D*D;
    const float* p3 = W + (3*NH+hh)*D*D;
    for (int idx = threadIdx.x; idx < D*D; idx += blockDim.x)
        Wo[idx] = w0*p0[idx] + w1*p1[idx] + w2*p2[idx] + w3*p3[idx];
}

// ---------------------------------------------------------------------------
// K2: uq[c] = q @ W1_[c] and t[c] = v @ W2_[c]
// ---------------------------------------------------------------------------
#define K2_ROWS 64
__global__ void __launch_bounds__(256) k_proj(const float* __restrict__ q,
                                              const float* __restrict__ v)
{
    __shared__ float qs[D*K2_ROWS];
    __shared__ float ws[D*D];

    int bid = blockIdx.x;
    int arr = bid >> 10;
    int c   = (bid >> 7) & 7;
    int bh  = (bid >> 3) & 15;
    int rc  = bid & 7;
    int tid = threadIdx.x;

    const float* inp = (arr ? v : q) + (bh*S + rc*K2_ROWS)*D;
    const float* Wm  = (arr ? g_W2m : g_W1m) + (c*NH + (bh & 7))*D*D;

    for (int idx = tid; idx < D*D; idx += 256)
        ws[idx] = Wm[idx];

    {
        int r = tid >> 2, mq = tid & 3;
        const float* rowp = inp + r*D + mq*16;
        #pragma unroll
        for (int m4 = 0; m4 < 4; m4++) {
            float4 vv = *(const float4*)(rowp + m4*4);
            int m = mq*16 + m4*4;
            qs[(m+0)*K2_ROWS + r] = vv.x;
            qs[(m+1)*K2_ROWS + r] = vv.y;
            qs[(m+2)*K2_ROWS + r] = vv.z;
            qs[(m+3)*K2_ROWS + r] = vv.w;
        }
    }
    __syncthreads();

    int tr = tid >> 3, tc = tid & 7;
    int r0 = tr*2, c0 = tc*8;
    u64 acc2[2][4];
    #pragma unroll
    for (int a = 0; a < 2; a++)
        #pragma unroll
        for (int p = 0; p < 4; p++) acc2[a][p] = 0ULL;

    #pragma unroll 8
    for (int m = 0; m < D; m++) {
        float2 av = *(const float2*)(qs + m*K2_ROWS + r0);
        const u64* wp = (const u64*)(ws + m*D + c0);
        u64 a0 = pk2f(av.x, av.x);
        u64 a1 = pk2f(av.y, av.y);
        fma2(acc2[0][0], wp[0], a0); fma2(acc2[0][1], wp[1], a0);
        fma2(acc2[0][2], wp[2], a0); fma2(acc2[0][3], wp[3], a0);
        fma2(acc2[1][0], wp[0], a1); fma2(acc2[1][1], wp[1], a1);
        fma2(acc2[1][2], wp[2], a1); fma2(acc2[1][3], wp[3], a1);
    }

    float* outb = (arr ? g_t : g_uq) + ((c*BH + bh)*S + rc*K2_ROWS)*D;
    #pragma unroll
    for (int a = 0; a < 2; a++) {
        float* o = outb + (r0+a)*D + c0;
        *(float4*)o     = make_float4(lo32(acc2[a][0]), hi32(acc2[a][0]),
                                      lo32(acc2[a][1]), hi32(acc2[a][1]));
        *(float4*)(o+4) = make_float4(lo32(acc2[a][2]), hi32(acc2[a][2]),
                                      lo32(acc2[a][3]), hi32(acc2[a][3]));
    }
}

// ---------------------------------------------------------------------------
// C1: scores + softmax -> g_P.  ITILE=16, RPW=2, 4 CTAs/SM (occ 50%).
// k-chunk register-prefetched (LDG overlaps previous chunk's compute);
// bmat codes prefetched one chunk ahead.
// ---------------------------------------------------------------------------
#define ITILE 16
#define RPW   2
#define UQP   66
#define KSP   66
#define SMEM_SC ((ITILE*NC*UQP + 64*KSP)*4)
__global__ void __launch_bounds__(256, 4) k_scores(const float* __restrict__ kk,
                                                   const int* __restrict__ bmat,
                                                   const float* __restrict__ rpb)
{
    extern __shared__ float sm[];
    float* uqs = sm;                       // [(i*8+c)*66 + n]
    float* ks  = sm + ITILE*NC*UQP;        // [j*66 + n]

    int bh = blockIdx.y;
    int i0 = blockIdx.x * ITILE;
    int b  = bh >> 3;
    int tid = threadIdx.x, w = tid >> 5, lane = tid & 31;
    int rows0 = w*RPW;

    // stage uq for 16 rows x 8 classes
    #pragma unroll
    for (int c = 0; c < NC; c++) {
        const float2* src = (const float2*)(g_uq + ((c*BH + bh)*S + i0)*D);
        #pragma unroll
        for (int idx2 = tid; idx2 < ITILE*32; idx2 += 256) {
            int i = idx2 >> 5, n2 = idx2 & 31;
            *(float2*)(uqs + (i*NC + c)*UQP + 2*n2) = src[idx2];
        }
    }

    const float2* kb2 = (const float2*)(kk + bh*S*D);

    // prologue prefetch: chunk 0 k-data and class codes
    float2 kreg[8];
    #pragma unroll
    for (int i = 0; i < 8; i++) kreg[i] = kb2[tid + i*256];
    int cc[2][RPW];
    #pragma unroll
    for (int g = 0; g < 2; g++)
        #pragma unroll
        for (int r = 0; r < RPW; r++)
            cc[g][r] = bmat[(b*S + i0 + rows0 + r)*S + g*32 + lane];

    float sc[RPW][16];

    #pragma unroll 1
    for (int ch = 0; ch < S/64; ch++) {
        __syncthreads();                       // ks free (prev compute done)
        #pragma unroll
        for (int i = 0; i < 8; i++) {
            int idx2 = tid + i*256;
            *(float2*)(ks + (idx2 >> 5)*KSP + 2*(idx2 & 31)) = kreg[i];
        }
        __syncthreads();

        int ccn[2][RPW];
        if (ch + 1 < S/64) {                   // prefetch next chunk
            #pragma unroll
            for (int i = 0; i < 8; i++) kreg[i] = kb2[(ch+1)*2048 + tid + i*256];
            #pragma unroll
            for (int g = 0; g < 2; g++)
                #pragma unroll
                for (int r = 0; r < RPW; r++)
                    ccn[g][r] = bmat[(b*S + i0 + rows0 + r)*S + (ch+1)*64 + g*32 + lane];
        }

        #pragma unroll
        for (int g = 0; g < 2; g++) {
            int jl = g*32 + lane;
            const u64* kbp = (const u64*)(ks + jl*KSP);
            const u64* ub[RPW];
            u64 acc[RPW];
            #pragma unroll
            for (int r = 0; r < RPW; r++) {
                ub[r]  = (const u64*)(uqs + ((rows0 + r)*NC + cc[g][r])*UQP);
                acc[r] = 0ULL;
            }
            #pragma unroll 16
            for (int n2 = 0; n2 < 32; n2++) {
                u64 k2 = kbp[n2];
                #pragma unroll
                for (int r = 0; r < RPW; r++)
                    fma2(acc[r], ub[r][n2], k2);
            }
            #pragma unroll
            for (int r = 0; r < RPW; r++)
                sc[r][ch*2 + g] = lo32(acc[r]) + hi32(acc[r]);
        }
        #pragma unroll
        for (int g = 0; g < 2; g++)
            #pragma unroll
            for (int r = 0; r < RPW; r++)
                cc[g][r] = ccn[g][r];
    }

    // softmax per row
    #pragma unroll
    for (int r = 0; r < RPW; r++) {
        int i = i0 + rows0 + r;
        const float* rp = rpb + (bh*S + i)*S;
        float mx = -1e30f;
        #pragma unroll
        for (int t = 0; t < 16; t++) {
            int j = (t >> 1)*64 + (t & 1)*32 + lane;
            sc[r][t] = sc[r][t]*0.125f + rp[j];
            mx = fmaxf(mx, sc[r][t]);
        }
        #pragma unroll
        for (int o = 16; o; o >>= 1) mx = fmaxf(mx, __shfl_xor_sync(0xffffffffu, mx, o));
        float ssum = 0.f;
        #pragma unroll
        for (int t = 0; t < 16; t++) { sc[r][t] = __expf(sc[r][t] - mx); ssum += sc[r][t]; }
        #pragma unroll
        for (int o = 16; o; o >>= 1) ssum += __shfl_xor_sync(0xffffffffu, ssum, o);
        float inv = __fdividef(1.f, ssum);
        float* pp = g_P + (bh*S + i)*S;
        #pragma unroll
        for (int t = 0; t < 16; t++) {
            int j = (t >> 1)*64 + (t & 1)*32 + lane;
            pp[j] = sc[r][t]*inv;
        }
    }
}

// ---------------------------------------------------------------------------
// C2: out[i,:] += sum_{j in split} P[i,j] * t[c_ij, j, :]
// 512 thr, launch_bounds(512,2) (regs<=64 -> 2 CTAs, occ 50%).
// Double-buffered t staging via cp.async; P/bmat register-prefetched.
// One __syncthreads per chunk; LDG latency hidden behind compute.
// ---------------------------------------------------------------------------
#define I2     64
#define JC2    16
#define JSPLIT 4
#define CHPB   (S/JC2/JSPLIT)     // 8 chunks per block
#define OTHR   512
#define TS_F   (NC*JC2*D)         // 8192 floats per t buffer
#define SMEM_OUT (2*TS_F*4 + 2*I2*JC2*8)   // 81920 B
__global__ void __launch_bounds__(OTHR, 2) k_out(const int* __restrict__ bmat,
                                                 float* __restrict__ out)
{
    extern __shared__ float smo[];
    float*  ts[2]  = { smo, smo + TS_F };
    float2* pcs[2] = { (float2*)(smo + 2*TS_F),
                       (float2*)(smo + 2*TS_F) + I2*JC2 };

    int bh    = blockIdx.y;
    int jblk  = blockIdx.x & (JSPLIT-1);
    int i0    = (blockIdx.x >> 2) * I2;
    int b     = bh >> 3;
    int tid = threadIdx.x, w = tid >> 5, lane = tid & 31;
    int half = lane >> 4, ln = lane & 15;

    const float* tb = g_t + bh*S*D;
    int j0base = jblk*CHPB*JC2;

    u64 accA[4], accB[4];
    #pragma unroll
    for (int r = 0; r < 4; r++) { accA[r] = 0ULL; accB[r] = 0ULL; }

    // prologue: stage chunk 0 (t via cp.async, P/bmat into regs)
    {
        int j0 = j0base;
        unsigned dst = (unsigned)__cvta_generic_to_shared(ts[0]);
        #pragma unroll
        for (int it = 0; it < 4; it++) {
            int idx = tid + it*OTHR;              // 0..2047 float4 slots
            int c = idx >> 8, r4 = idx & 255;
            cpa16(dst + idx*16, tb + (c*BH*S + j0)*D + r4*4);
        }
        cpa_commit();
    }
    float pf_p[2]; int pf_c[2];
    #pragma unroll
    for (int it = 0; it < 2; it++) {
        int idx = tid + it*OTHR;
        int ii = idx >> 4, jj = idx & 15;
        pf_p[it] = g_P [(bh*S + i0 + ii)*S + j0base + jj];
        pf_c[it] = bmat[(b *S + i0 + ii)*S + j0base + jj];
    }

    #pragma unroll 1
    for (int chl = 0; chl < CHPB; chl++) {
        int cur = chl & 1, nxt = cur ^ 1;
        // store prefetched P/class into pcs[cur]
        #pragma unroll
        for (int it = 0; it < 2; it++) {
            int idx = tid + it*OTHR;
            pcs[cur][idx] = make_float2(pf_p[it],
                                        __int_as_float(pf_c[it]*(JC2*D*4)));
        }
        cpa_wait0();
        __syncthreads();

        if (chl + 1 < CHPB) {                      // stage next chunk
            int j0n = j0base + (chl+1)*JC2;
            unsigned dst = (unsigned)__cvta_generic_to_shared(ts[nxt]);
            #pragma unroll
            for (int it = 0; it < 4; it++) {
                int idx = tid + it*OTHR;
                int c = idx >> 8, r4 = idx & 255;
                cpa16(dst + idx*16, tb + (c*BH*S + j0n)*D + r4*4);
            }
            cpa_commit();
            #pragma unroll
            for (int it = 0; it < 2; it++) {
                int idx = tid + it*OTHR;
                int ii = idx >> 4, jj = idx & 15;
                pf_p[it] = g_P [(bh*S + i0 + ii)*S + j0n + jj];
                pf_c[it] = bmat[(b *S + i0 + ii)*S + j0n + jj];
            }
        }

        const char* tsc = (const char*)ts[cur];
        const float2* pcc = pcs[cur];
        #pragma unroll
        for (int r = 0; r < 4; r++) {
            int il = w*4 + r;
            #pragma unroll
            for (int jp = 0; jp < JC2; jp += 2) {
                float2 pc = pcc[il*JC2 + jp + half];
                int coff = __float_as_int(pc.y);
                const float4 tv = *(const float4*)(tsc + coff
                                                   + (jp + half)*(D*4) + ln*16);
                u64 pk = pk2f(pc.x, pc.x);
                fma2(accA[r], pk2f(tv.x, tv.y), pk);
                fma2(accB[r], pk2f(tv.z, tv.w), pk);
            }
        }
    }

    #pragma unroll
    for (int r = 0; r < 4; r++) {
        float x = lo32(accA[r]), y = hi32(accA[r]);
        float z = lo32(accB[r]), u = hi32(accB[r]);
        x += __shfl_xor_sync(0xffffffffu, x, 16);
        y += __shfl_xor_sync(0xffffffffu, y, 16);
        z += __shfl_xor_sync(0xffffffffu, z, 16);
        u += __shfl_xor_sync(0xffffffffu, u, 16);
        int ii = i0 + w*4 + r;
        float* o = out + (bh*S + ii)*D + ln*4;
        if (half == 0) { atomicAdd(o,     x); atomicAdd(o + 1, y); }
        else           { atomicAdd(o + 2, z); atomicAdd(o + 3, u); }
    }
}

// ---------------------------------------------------------------------------
extern "C" void kernel_launch(void* const* d_in, const int* in_sizes, int n_in,
                              void* d_out, int out_size)
{
    const float* q   = (const float*)d_in[0];
    const float* k   = (const float*)d_in[1];
    const float* v   = (const float*)d_in[2];
    const int*   bm  = (const int*)  d_in[3];
    const float* rpb = (const float*)d_in[4];
    const float* W1  = (const float*)d_in[5];
    const float* A1  = (const float*)d_in[6];
    const float* W2  = (const float*)d_in[7];
    const float* A2  = (const float*)d_in[8];
    (void)in_sizes; (void)n_in; (void)out_size;   // mask (d_in[9]) is all-True

    cudaFuncSetAttribute(k_scores, cudaFuncAttributeMaxDynamicSharedMemorySize,
                         SMEM_SC);
    cudaFuncSetAttribute(k_out, cudaFuncAttributeMaxDynamicSharedMemorySize,
                         SMEM_OUT);

    k_mixw  <<<128, 256>>>(W1, A1, W2, A2, (float4*)d_out);
    k_proj  <<<2*NC*BH*(S/K2_ROWS), 256>>>(q, v);
    k_scores<<<dim3(S/ITILE, BH), 256, SMEM_SC>>>(k, bm, rpb);
    k_out   <<<dim3((S/I2)*JSPLIT, BH), OTHR, SMEM_OUT>>>(bm, (float*)d_out);
}

// round 8
// speedup vs baseline: 1.6503x; 1.6503x over previous
#include <cuda_runtime.h>

#define BATCH 2
#define NH    8
#define S     512
#define D     64
#define NC    8
#define NB    4
#define BH    (BATCH*NH)

// Scratch (device globals: allocation rules forbid cudaMalloc)
__device__ float g_W1m[NC*NH*D*D];      // mixed W1_ [c][h][m][n]
__device__ float g_W2m[NC*NH*D*D];      // mixed W2_ [c][h][d][D]
__device__ float g_uq [NC*BH*S*D];      // q @ W1_[c]  : [c][bh][i][n]
__device__ float g_t  [NC*BH*S*D];      // v @ W2_[c]  : [c][bh][j][Dd]
__device__ float g_P  [BH*S*S];         // softmax probabilities [bh][i][j]

typedef unsigned long long u64;

// ---- f32x2 helpers (packed fp32 pair math; FFMA2 only reachable via PTX) ----
__device__ __forceinline__ u64 pk2f(float x, float y) {
    u64 r; asm("mov.b64 %0, {%1, %2};" : "=l"(r) : "f"(x), "f"(y)); return r;
}
__device__ __forceinline__ void fma2(u64& acc, u64 a, u64 b) {
    asm("fma.rn.f32x2 %0, %1, %2, %0;" : "+l"(acc) : "l"(a), "l"(b));
}
__device__ __forceinline__ float lo32(u64 v) {
    return __int_as_float((int)(unsigned)(v & 0xffffffffULL));
}
__device__ __forceinline__ float hi32(u64 v) {
    return __int_as_float((int)(unsigned)(v >> 32));
}

// ---------------------------------------------------------------------------
// K1: mix the B bases into C class matrices; also zero d_out (poisoned).
// ---------------------------------------------------------------------------
__global__ void k_mixw(const float* __restrict__ W1, const float* __restrict__ A1,
                       const float* __restrict__ W2, const float* __restrict__ A2,
                       float4* __restrict__ outz)
{
    for (int i = blockIdx.x*256 + threadIdx.x; i < BH*S*D/4; i += 128*256)
        outz[i] = make_float4(0.f,0.f,0.f,0.f);

    int arr = blockIdx.x >> 6;
    int c   = (blockIdx.x >> 3) & 7;
    int hh  = blockIdx.x & 7;
    const float* W = arr ? W2 : W1;
    const float* A = arr ? A2 : A1;
    float* Wo = (arr ? g_W2m : g_W1m) + (c*NH + hh)*D*D;

    __shared__ float wsm[NB];
    if (threadIdx.x == 0) {
        float av[NB]; float mx = -1e30f;
        #pragma unroll
        for (int bb = 0; bb < NB; bb++) { av[bb] = A[(c*NB+bb)*NH + hh]; mx = fmaxf(mx, av[bb]); }
        float ssum = 0.f;
        #pragma unroll
        for (int bb = 0; bb < NB; bb++) { av[bb] = __expf(av[bb]-mx); ssum += av[bb]; }
        #pragma unroll
        for (int bb = 0; bb < NB; bb++) wsm[bb] = av[bb]/ssum;
    }
    __syncthreads();
    float w0 = wsm[0], w1 = wsm[1], w2 = wsm[2], w3 = wsm[3];
    const float* p0 = W + (0*NH+hh)*D*D;
    const float* p1 = W + (1*NH+hh)*D*D;
    const float* p2 = W + (2*NH+hh)*D*D;
    const float* p3 = W + (3*NH+hh)*D*D;
    for (int idx = threadIdx.x; idx < D*D; idx += blockDim.x)
        Wo[idx] = w0*p0[idx] + w1*p1[idx] + w2*p2[idx] + w3*p3[idx];
}

// ---------------------------------------------------------------------------
// K2: uq[c] = q @ W1_[c] and t[c] = v @ W2_[c]   (512x64 @ 64x64 per (c,bh))
// ---------------------------------------------------------------------------
#define K2_ROWS 64
__global__ void __launch_bounds__(256) k_proj(const float* __restrict__ q,
                                              const float* __restrict__ v)
{
    __shared__ float qs[D*K2_ROWS];
    __shared__ float ws[D*D];

    int bid = blockIdx.x;
    int arr = bid >> 10;
    int c   = (bid >> 7) & 7;
    int bh  = (bid >> 3) & 15;
    int rc  = bid & 7;
    int tid = threadIdx.x;

    const float* inp = (arr ? v : q) + (bh*S + rc*K2_ROWS)*D;
    const float* Wm  = (arr ? g_W2m : g_W1m) + (c*NH + (bh & 7))*D*D;

    for (int idx = tid; idx < D*D; idx += 256)
        ws[idx] = Wm[idx];

    {
        int r = tid >> 2, mq = tid & 3;
        const float* rowp = inp + r*D + mq*16;
        #pragma unroll
        for (int m4 = 0; m4 < 4; m4++) {
            float4 vv = *(const float4*)(rowp + m4*4);
            int m = mq*16 + m4*4;
            qs[(m+0)*K2_ROWS + r] = vv.x;
            qs[(m+1)*K2_ROWS + r] = vv.y;
            qs[(m+2)*K2_ROWS + r] = vv.z;
            qs[(m+3)*K2_ROWS + r] = vv.w;
        }
    }
    __syncthreads();

    int tr = tid >> 3, tc = tid & 7;
    int r0 = tr*2, c0 = tc*8;
    u64 acc2[2][4];
    #pragma unroll
    for (int a = 0; a < 2; a++)
        #pragma unroll
        for (int p = 0; p < 4; p++) acc2[a][p] = 0ULL;

    #pragma unroll 8
    for (int m = 0; m < D; m++) {
        float2 av = *(const float2*)(qs + m*K2_ROWS + r0);
        const u64* wp = (const u64*)(ws + m*D + c0);
        u64 a0 = pk2f(av.x, av.x);
        u64 a1 = pk2f(av.y, av.y);
        fma2(acc2[0][0], wp[0], a0); fma2(acc2[0][1], wp[1], a0);
        fma2(acc2[0][2], wp[2], a0); fma2(acc2[0][3], wp[3], a0);
        fma2(acc2[1][0], wp[0], a1); fma2(acc2[1][1], wp[1], a1);
        fma2(acc2[1][2], wp[2], a1); fma2(acc2[1][3], wp[3], a1);
    }

    float* outb = (arr ? g_t : g_uq) + ((c*BH + bh)*S + rc*K2_ROWS)*D;
    #pragma unroll
    for (int a = 0; a < 2; a++) {
        float* o = outb + (r0+a)*D + c0;
        *(float4*)o     = make_float4(lo32(acc2[a][0]), hi32(acc2[a][0]),
                                      lo32(acc2[a][1]), hi32(acc2[a][1]));
        *(float4*)(o+4) = make_float4(lo32(acc2[a][2]), hi32(acc2[a][2]),
                                      lo32(acc2[a][3]), hi32(acc2[a][3]));
    }
}

// ---------------------------------------------------------------------------
// C1: scores (class-gathered dot) + row softmax -> g_P   (R4 configuration)
// Block = (bh, i-tile of 32); warp handles 4 rows; lanes over j; f32x2 over
// n-pairs. uqs[i][c][pitch 66]; ks[j][pitch 66]. Dynamic smem 84480B, 2 CTA/SM.
// ---------------------------------------------------------------------------
#define ITILE 32
#define RPW   4
#define UQP   66
#define KSP   66
#define SMEM_SC ((ITILE*NC*UQP + 64*KSP)*4)
__global__ void __launch_bounds__(256) k_scores(const float* __restrict__ kk,
                                                const int* __restrict__ bmat,
                                                const float* __restrict__ rpb)
{
    extern __shared__ float sm[];
    float* uqs = sm;                       // [(i*8+c)*66 + n]
    float* ks  = sm + ITILE*NC*UQP;        // [j*66 + n]

    int bh = blockIdx.y;
    int i0 = blockIdx.x * ITILE;
    int b  = bh >> 3;
    int tid = threadIdx.x, w = tid >> 5, lane = tid & 31;
    int rows0 = w*RPW;

    // stage uq for 32 rows x 8 classes
    #pragma unroll
    for (int c = 0; c < NC; c++) {
        const float2* src = (const float2*)(g_uq + ((c*BH + bh)*S + i0)*D);
        for (int idx2 = tid; idx2 < ITILE*32; idx2 += 256) {
            int i = idx2 >> 5, n2 = idx2 & 31;
            *(float2*)(uqs + (i*NC + c)*UQP + 2*n2) = src[idx2];
        }
    }

    float sc[RPW][16];

    #pragma unroll 1
    for (int ch = 0; ch < S/64; ch++) {
        // prefetch class codes for both j-groups (latency hidden by staging)
        int cc[2][RPW];
        #pragma unroll
        for (int g = 0; g < 2; g++)
            #pragma unroll
            for (int r = 0; r < RPW; r++)
                cc[g][r] = bmat[(b*S + i0 + rows0 + r)*S + ch*64 + g*32 + lane];

        __syncthreads();
        {   // stage k chunk [64 j][64 n]
            const float2* kb2 = (const float2*)(kk + (bh*S + ch*64)*D);
            for (int idx2 = tid; idx2 < 64*32; idx2 += 256) {
                int j = idx2 >> 5, n2 = idx2 & 31;
                *(float2*)(ks + j*KSP + 2*n2) = kb2[idx2];
            }
        }
        __syncthreads();

        #pragma unroll
        for (int g = 0; g < 2; g++) {
            int jl = g*32 + lane;
            const u64* kbp = (const u64*)(ks + jl*KSP);
            const u64* ub[RPW];
            u64 acc[RPW];
            #pragma unroll
            for (int r = 0; r < RPW; r++) {
                ub[r]  = (const u64*)(uqs + ((rows0 + r)*NC + cc[g][r])*UQP);
                acc[r] = 0ULL;
            }
            #pragma unroll 16
            for (int n2 = 0; n2 < 32; n2++) {
                u64 k2 = kbp[n2];
                #pragma unroll
                for (int r = 0; r < RPW; r++)
                    fma2(acc[r], ub[r][n2], k2);
            }
            #pragma unroll
            for (int r = 0; r < RPW; r++)
                sc[r][ch*2 + g] = lo32(acc[r]) + hi32(acc[r]);
        }
    }

    // softmax per row
    #pragma unroll
    for (int r = 0; r < RPW; r++) {
        int i = i0 + rows0 + r;
        const float* rp = rpb + (bh*S + i)*S;
        float mx = -1e30f;
        #pragma unroll
        for (int t = 0; t < 16; t++) {
            int j = (t >> 1)*64 + (t & 1)*32 + lane;
            sc[r][t] = sc[r][t]*0.125f + rp[j];
            mx = fmaxf(mx, sc[r][t]);
        }
        #pragma unroll
        for (int o = 16; o; o >>= 1) mx = fmaxf(mx, __shfl_xor_sync(0xffffffffu, mx, o));
        float ssum = 0.f;
        #pragma unroll
        for (int t = 0; t < 16; t++) { sc[r][t] = __expf(sc[r][t] - mx); ssum += sc[r][t]; }
        #pragma unroll
        for (int o = 16; o; o >>= 1) ssum += __shfl_xor_sync(0xffffffffu, ssum, o);
        float inv = __fdividef(1.f, ssum);
        float* pp = g_P + (bh*S + i)*S;
        #pragma unroll
        for (int t = 0; t < 16; t++) {
            int j = (t >> 1)*64 + (t & 1)*32 + lane;
            pp[j] = sc[r][t]*inv;
        }
    }
}

// ---------------------------------------------------------------------------
// C2: out[i,:] += sum_{j in split} P[i,j] * t[c_ij, j, :]   (R4 structure)
// JSPLIT=8: 1024 blocks (smaller tail, better latency hiding); pair offset
// (class*8192 + j*256) fully precomputed at staging -> inner addr = 1 IADD3.
// ---------------------------------------------------------------------------
#define I2     64
#define JC2    16
#define JSPLIT 8
#define CHPB   (S/JC2/JSPLIT)     // 4 chunks per block
__global__ void __launch_bounds__(256) k_out(const int* __restrict__ bmat,
                                             float* __restrict__ out)
{
    __shared__ float  ts[NC*JC2*D];   // 32KB  [c][j][d]
    __shared__ float2 pcs[I2*JC2];    // 8KB   {p, byte-offset(c,j) as bits}

    int bh    = blockIdx.y;
    int jblk  = blockIdx.x & (JSPLIT-1);
    int i0    = (blockIdx.x >> 3) * I2;
    int b     = bh >> 3;
    int tid = threadIdx.x, w = tid >> 5, lane = tid & 31;
    int half = lane >> 4, ln = lane & 15;
    int lnoff = ln*16;

    u64 accA[8], accB[8];
    #pragma unroll
    for (int r = 0; r < 8; r++) { accA[r] = 0ULL; accB[r] = 0ULL; }

    #pragma unroll 1
    for (int chl = 0; chl < CHPB; chl++) {
        int ch = jblk*CHPB + chl;
        int j0 = ch*JC2;
        __syncthreads();
        #pragma unroll
        for (int c = 0; c < NC; c++) {
            const float4* src = (const float4*)(g_t + ((c*BH + bh)*S + j0)*D);
            float4* dst = (float4*)(ts + c*JC2*D);
            dst[tid] = src[tid];                 // JC2*D/4 == 256 == blockDim
        }
        for (int idx = tid; idx < I2*JC2; idx += 256) {
            int ii = idx >> 4, jj = idx & 15;
            float p = g_P [(bh*S + i0 + ii)*S + j0 + jj];
            int   c = bmat[(b *S + i0 + ii)*S + j0 + jj];
            pcs[idx] = make_float2(p, __int_as_float(c*(JC2*D*4) + jj*(D*4)));
        }
        __syncthreads();
        #pragma unroll
        for (int r = 0; r < 8; r++) {
            int il = w*8 + r;
            #pragma unroll
            for (int jp = 0; jp < JC2; jp += 2) {
                float2 pc = pcs[il*JC2 + jp + half];
                int off = __float_as_int(pc.y);
                const float4 tv = *(const float4*)((const char*)ts + off + lnoff);
                u64 pk = pk2f(pc.x, pc.x);
                fma2(accA[r], pk2f(tv.x, tv.y), pk);
                fma2(accB[r], pk2f(tv.z, tv.w), pk);
            }
        }
    }

    #pragma unroll
    for (int r = 0; r < 8; r++) {
        float x = lo32(accA[r]), y = hi32(accA[r]);
        float z = lo32(accB[r]), u = hi32(accB[r]);
        x += __shfl_xor_sync(0xffffffffu, x, 16);
        y += __shfl_xor_sync(0xffffffffu, y, 16);
        z += __shfl_xor_sync(0xffffffffu, z, 16);
        u += __shfl_xor_sync(0xffffffffu, u, 16);
        int ii = i0 + w*8 + r;
        float* o = out + (bh*S + ii)*D + ln*4;
        if (half == 0) { atomicAdd(o,     x); atomicAdd(o + 1, y); }
        else           { atomicAdd(o + 2, z); atomicAdd(o + 3, u); }
    }
}

// ---------------------------------------------------------------------------
extern "C" void kernel_launch(void* const* d_in, const int* in_sizes, int n_in,
                              void* d_out, int out_size)
{
    const float* q   = (const float*)d_in[0];
    const float* k   = (const float*)d_in[1];
    const float* v   = (const float*)d_in[2];
    const int*   bm  = (const int*)  d_in[3];
    const float* rpb = (const float*)d_in[4];
    const float* W1  = (const float*)d_in[5];
    const float* A1  = (const float*)d_in[6];
    const float* W2  = (const float*)d_in[7];
    const float* A2  = (const float*)d_in[8];
    (void)in_sizes; (void)n_in; (void)out_size;   // mask (d_in[9]) is all-True

    cudaFuncSetAttribute(k_scores, cudaFuncAttributeMaxDynamicSharedMemorySize,
                         SMEM_SC);

    k_mixw  <<<128, 256>>>(W1, A1, W2, A2, (float4*)d_out);
    k_proj  <<<2*NC*BH*(S/K2_ROWS), 256>>>(q, v);
    k_scores<<<dim3(S/ITILE, BH), 256, SMEM_SC>>>(k, bm, rpb);
    k_out   <<<dim3((S/I2)*JSPLIT, BH), 256>>>(bm, (float*)d_out);
}

// round 9
// speedup vs baseline: 1.8884x; 1.1443x over previous
#include <cuda_runtime.h>
#include <cuda_fp16.h>

#define BATCH 2
#define NH    8
#define S     512
#define D     64
#define NC    8
#define NB    4
#define BH    (BATCH*NH)

// Scratch (device globals: allocation rules forbid cudaMalloc)
__device__ float  g_W1m[NC*NH*D*D];     // mixed W1_ [c][h][m][n]
__device__ float  g_W2m[NC*NH*D*D];     // mixed W2_ [c][h][d][D]
__device__ float  g_uq [NC*BH*S*D];     // q @ W1_[c]  : [c][bh][i][n]  (fp32)
__device__ __half g_th [NC*BH*S*D];     // v @ W2_[c]  : [c][bh][j][d]  (fp16)
__device__ float  g_P  [BH*S*S];        // softmax probabilities [bh][i][j]

typedef unsigned long long u64;

// ---- f32x2 helpers (packed fp32 pair math; FFMA2 only reachable via PTX) ----
__device__ __forceinline__ u64 pk2f(float x, float y) {
    u64 r; asm("mov.b64 %0, {%1, %2};" : "=l"(r) : "f"(x), "f"(y)); return r;
}
__device__ __forceinline__ void fma2(u64& acc, u64 a, u64 b) {
    asm("fma.rn.f32x2 %0, %1, %2, %0;" : "+l"(acc) : "l"(a), "l"(b));
}
__device__ __forceinline__ float lo32(u64 v) {
    return __int_as_float((int)(unsigned)(v & 0xffffffffULL));
}
__device__ __forceinline__ float hi32(u64 v) {
    return __int_as_float((int)(unsigned)(v >> 32));
}

struct __align__(16) H8 { __half2 h[4]; };

// ---------------------------------------------------------------------------
// K1: mix the B bases into C class matrices; also zero d_out (poisoned).
// ---------------------------------------------------------------------------
__global__ void k_mixw(const float* __restrict__ W1, const float* __restrict__ A1,
                       const float* __restrict__ W2, const float* __restrict__ A2,
                       float4* __restrict__ outz)
{
    for (int i = blockIdx.x*256 + threadIdx.x; i < BH*S*D/4; i += 128*256)
        outz[i] = make_float4(0.f,0.f,0.f,0.f);

    int arr = blockIdx.x >> 6;
    int c   = (blockIdx.x >> 3) & 7;
    int hh  = blockIdx.x & 7;
    const float* W = arr ? W2 : W1;
    const float* A = arr ? A2 : A1;
    float* Wo = (arr ? g_W2m : g_W1m) + (c*NH + hh)*D*D;

    __shared__ float wsm[NB];
    if (threadIdx.x == 0) {
        float av[NB]; float mx = -1e30f;
        #pragma unroll
        for (int bb = 0; bb < NB; bb++) { av[bb] = A[(c*NB+bb)*NH + hh]; mx = fmaxf(mx, av[bb]); }
        float ssum = 0.f;
        #pragma unroll
        for (int bb = 0; bb < NB; bb++) { av[bb] = __expf(av[bb]-mx); ssum += av[bb]; }
        #pragma unroll
        for (int bb = 0; bb < NB; bb++) wsm[bb] = av[bb]/ssum;
    }
    __syncthreads();
    float w0 = wsm[0], w1 = wsm[1], w2 = wsm[2], w3 = wsm[3];
    const float* p0 = W + (0*NH+hh)*D*D;
    const float* p1 = W + (1*NH+hh)*D*D;
    const float* p2 = W + (2*NH+hh)*D*D;
    const float* p3 = W + (3*NH+hh)*D*D;
    for (int idx = threadIdx.x; idx < D*D; idx += blockDim.x)
        Wo[idx] = w0*p0[idx] + w1*p1[idx] + w2*p2[idx] + w3*p3[idx];
}

// ---------------------------------------------------------------------------
// K2: uq[c] = q @ W1_[c] (fp32 out) and t[c] = v @ W2_[c] (fp16 out)
// ---------------------------------------------------------------------------
#define K2_ROWS 64
__global__ void __launch_bounds__(256) k_proj(const float* __restrict__ q,
                                              const float* __restrict__ v)
{
    __shared__ float qs[D*K2_ROWS];
    __shared__ float ws[D*D];

    int bid = blockIdx.x;
    int arr = bid >> 10;
    int c   = (bid >> 7) & 7;
    int bh  = (bid >> 3) & 15;
    int rc  = bid & 7;
    int tid = threadIdx.x;

    const float* inp = (arr ? v : q) + (bh*S + rc*K2_ROWS)*D;
    const float* Wm  = (arr ? g_W2m : g_W1m) + (c*NH + (bh & 7))*D*D;

    for (int idx = tid; idx < D*D; idx += 256)
        ws[idx] = Wm[idx];

    {
        int r = tid >> 2, mq = tid & 3;
        const float* rowp = inp + r*D + mq*16;
        #pragma unroll
        for (int m4 = 0; m4 < 4; m4++) {
            float4 vv = *(const float4*)(rowp + m4*4);
            int m = mq*16 + m4*4;
            qs[(m+0)*K2_ROWS + r] = vv.x;
            qs[(m+1)*K2_ROWS + r] = vv.y;
            qs[(m+2)*K2_ROWS + r] = vv.z;
            qs[(m+3)*K2_ROWS + r] = vv.w;
        }
    }
    __syncthreads();

    int tr = tid >> 3, tc = tid & 7;
    int r0 = tr*2, c0 = tc*8;
    u64 acc2[2][4];
    #pragma unroll
    for (int a = 0; a < 2; a++)
        #pragma unroll
        for (int p = 0; p < 4; p++) acc2[a][p] = 0ULL;

    #pragma unroll 8
    for (int m = 0; m < D; m++) {
        float2 av = *(const float2*)(qs + m*K2_ROWS + r0);
        const u64* wp = (const u64*)(ws + m*D + c0);
        u64 a0 = pk2f(av.x, av.x);
        u64 a1 = pk2f(av.y, av.y);
        fma2(acc2[0][0], wp[0], a0); fma2(acc2[0][1], wp[1], a0);
        fma2(acc2[0][2], wp[2], a0); fma2(acc2[0][3], wp[3], a0);
        fma2(acc2[1][0], wp[0], a1); fma2(acc2[1][1], wp[1], a1);
        fma2(acc2[1][2], wp[2], a1); fma2(acc2[1][3], wp[3], a1);
    }

    if (arr == 0) {
        float* outb = g_uq + ((c*BH + bh)*S + rc*K2_ROWS)*D;
        #pragma unroll
        for (int a = 0; a < 2; a++) {
            float* o = outb + (r0+a)*D + c0;
            *(float4*)o     = make_float4(lo32(acc2[a][0]), hi32(acc2[a][0]),
                                          lo32(acc2[a][1]), hi32(acc2[a][1]));
            *(float4*)(o+4) = make_float4(lo32(acc2[a][2]), hi32(acc2[a][2]),
                                          lo32(acc2[a][3]), hi32(acc2[a][3]));
        }
    } else {
        __half* outb = g_th + ((c*BH + bh)*S + rc*K2_ROWS)*D;
        #pragma unroll
        for (int a = 0; a < 2; a++) {
            H8 hv;
            #pragma unroll
            for (int p = 0; p < 4; p++)
                hv.h[p] = __floats2half2_rn(lo32(acc2[a][p]), hi32(acc2[a][p]));
            *(H8*)(outb + (r0+a)*D + c0) = hv;
        }
    }
}

// ---------------------------------------------------------------------------
// C1: scores (class-gathered dot) + row softmax -> g_P
// float4 inner (pitch 68: c/j stride = 4 banks -> conflict-free per 8-lane
// phase); k-chunk register-prefetched (LDG overlaps previous chunk compute).
// ITILE=32, RPW=4, smem 87040B (2 CTA/SM).
// ---------------------------------------------------------------------------
#define ITILE 32
#define RPW   4
#define UQP   68
#define KSP   68
#define SMEM_SC ((ITILE*NC*UQP + 64*KSP)*4)
__global__ void __launch_bounds__(256) k_scores(const float* __restrict__ kk,
                                                const int* __restrict__ bmat,
                                                const float* __restrict__ rpb)
{
    extern __shared__ float sm[];
    float* uqs = sm;                       // [(i*8+c)*68 + n]
    float* ks  = sm + ITILE*NC*UQP;        // [j*68 + n]

    int bh = blockIdx.y;
    int i0 = blockIdx.x * ITILE;
    int b  = bh >> 3;
    int tid = threadIdx.x, w = tid >> 5, lane = tid & 31;
    int rows0 = w*RPW;

    // stage uq for 32 rows x 8 classes (float4)
    #pragma unroll
    for (int c = 0; c < NC; c++) {
        const float4* src = (const float4*)(g_uq + ((c*BH + bh)*S + i0)*D);
        for (int idx = tid; idx < ITILE*16; idx += 256) {
            int i = idx >> 4, n4 = idx & 15;
            *(float4*)(uqs + (i*NC + c)*UQP + 4*n4) = src[idx];
        }
    }

    const float4* kb4 = (const float4*)(kk + bh*S*D);

    // prologue: prefetch chunk 0 k-data into registers
    float4 kreg[4];
    #pragma unroll
    for (int i = 0; i < 4; i++) kreg[i] = kb4[tid + i*256];

    float sc[RPW][16];

    #pragma unroll 1
    for (int ch = 0; ch < S/64; ch++) {
        // prefetch class codes (hidden behind staging)
        int cc[2][RPW];
        #pragma unroll
        for (int g = 0; g < 2; g++)
            #pragma unroll
            for (int r = 0; r < RPW; r++)
                cc[g][r] = bmat[(b*S + i0 + rows0 + r)*S + ch*64 + g*32 + lane];

        __syncthreads();
        #pragma unroll
        for (int i = 0; i < 4; i++) {
            int idx = tid + i*256;                // j = idx>>4, n4 = idx&15
            *(float4*)(ks + (idx >> 4)*KSP + 4*(idx & 15)) = kreg[i];
        }
        __syncthreads();

        if (ch + 1 < S/64) {                      // prefetch next k chunk
            #pragma unroll
            for (int i = 0; i < 4; i++) kreg[i] = kb4[(ch+1)*1024 + tid + i*256];
        }

        #pragma unroll
        for (int g = 0; g < 2; g++) {
            int jl = g*32 + lane;
            const float4* kbp4 = (const float4*)(ks + jl*KSP);
            const float4* ub4[RPW];
            u64 acc[RPW];
            #pragma unroll
            for (int r = 0; r < RPW; r++) {
                ub4[r] = (const float4*)(uqs + ((rows0 + r)*NC + cc[g][r])*UQP);
                acc[r] = 0ULL;
            }
            #pragma unroll
            for (int n4 = 0; n4 < 16; n4++) {
                float4 kv = kbp4[n4];
                u64 k01 = pk2f(kv.x, kv.y);
                u64 k23 = pk2f(kv.z, kv.w);
                #pragma unroll
                for (int r = 0; r < RPW; r++) {
                    float4 uv = ub4[r][n4];
                    fma2(acc[r], pk2f(uv.x, uv.y), k01);
                    fma2(acc[r], pk2f(uv.z, uv.w), k23);
                }
            }
            #pragma unroll
            for (int r = 0; r < RPW; r++)
                sc[r][ch*2 + g] = lo32(acc[r]) + hi32(acc[r]);
        }
    }

    // softmax per row
    #pragma unroll
    for (int r = 0; r < RPW; r++) {
        int i = i0 + rows0 + r;
        const float* rp = rpb + (bh*S + i)*S;
        float mx = -1e30f;
        #pragma unroll
        for (int t = 0; t < 16; t++) {
            int j = (t >> 1)*64 + (t & 1)*32 + lane;
            sc[r][t] = sc[r][t]*0.125f + rp[j];
            mx = fmaxf(mx, sc[r][t]);
        }
        #pragma unroll
        for (int o = 16; o; o >>= 1) mx = fmaxf(mx, __shfl_xor_sync(0xffffffffu, mx, o));
        float ssum = 0.f;
        #pragma unroll
        for (int t = 0; t < 16; t++) { sc[r][t] = __expf(sc[r][t] - mx); ssum += sc[r][t]; }
        #pragma unroll
        for (int o = 16; o; o >>= 1) ssum += __shfl_xor_sync(0xffffffffu, ssum, o);
        float inv = __fdividef(1.f, ssum);
        float* pp = g_P + (bh*S + i)*S;
        #pragma unroll
        for (int t = 0; t < 16; t++) {
            int j = (t >> 1)*64 + (t & 1)*32 + lane;
            pp[j] = sc[r][t]*inv;
        }
    }
}

// ---------------------------------------------------------------------------
// C2: out[i,:] += sum_{j in split} P[i,j] * t_h[c_ij, j, :]   (t in fp16)
// tv LDS halves to 2 wavefronts/iter; restage traffic halves.
// ---------------------------------------------------------------------------
#define I2     64
#define JC2    16
#define JSPLIT 8
#define CHPB   (S/JC2/JSPLIT)     // 4 chunks per block
__global__ void __launch_bounds__(256) k_out(const int* __restrict__ bmat,
                                             float* __restrict__ out)
{
    __shared__ __half  tsh[NC*JC2*D]; // 16KB  [c][j][d]
    __shared__ float2  pcs[I2*JC2];   // 8KB   {p, byte-offset(c,j) as bits}

    int bh    = blockIdx.y;
    int jblk  = blockIdx.x & (JSPLIT-1);
    int i0    = (blockIdx.x >> 3) * I2;
    int b     = bh >> 3;
    int tid = threadIdx.x, w = tid >> 5, lane = tid & 31;
    int half = lane >> 4, ln = lane & 15;
    int lnoff = ln*8;

    u64 accA[8], accB[8];
    #pragma unroll
    for (int r = 0; r < 8; r++) { accA[r] = 0ULL; accB[r] = 0ULL; }

    #pragma unroll 1
    for (int chl = 0; chl < CHPB; chl++) {
        int ch = jblk*CHPB + chl;
        int j0 = ch*JC2;
        __syncthreads();
        // stage t (fp16): NC*JC2*D halves = 1024 uint4, 4 per thread
        #pragma unroll
        for (int idx = tid; idx < NC*JC2*D/8; idx += 256) {
            int c = idx >> 7, r8 = idx & 127;
            ((uint4*)tsh)[idx] =
                ((const uint4*)(g_th + ((c*BH + bh)*S + j0)*D))[r8];
        }
        for (int idx = tid; idx < I2*JC2; idx += 256) {
            int ii = idx >> 4, jj = idx & 15;
            float p = g_P [(bh*S + i0 + ii)*S + j0 + jj];
            int   c = bmat[(b *S + i0 + ii)*S + j0 + jj];
            pcs[idx] = make_float2(p, __int_as_float(c*(JC2*D*2) + jj*(D*2)));
        }
        __syncthreads();
        #pragma unroll
        for (int r = 0; r < 8; r++) {
            int il = w*8 + r;
            #pragma unroll
            for (int jp = 0; jp < JC2; jp += 2) {
                float2 pc = pcs[il*JC2 + jp + half];
                int off = __float_as_int(pc.y);
                uint2 uv = *(const uint2*)((const char*)tsh + off + lnoff);
                float2 f0 = __half22float2(*(const __half2*)&uv.x);
                float2 f1 = __half22float2(*(const __half2*)&uv.y);
                u64 pk = pk2f(pc.x, pc.x);
                fma2(accA[r], pk2f(f0.x, f0.y), pk);
                fma2(accB[r], pk2f(f1.x, f1.y), pk);
            }
        }
    }

    #pragma unroll
    for (int r = 0; r < 8; r++) {
        float x = lo32(accA[r]), y = hi32(accA[r]);
        float z = lo32(accB[r]), u = hi32(accB[r]);
        x += __shfl_xor_sync(0xffffffffu, x, 16);
        y += __shfl_xor_sync(0xffffffffu, y, 16);
        z += __shfl_xor_sync(0xffffffffu, z, 16);
        u += __shfl_xor_sync(0xffffffffu, u, 16);
        int ii = i0 + w*8 + r;
        float* o = out + (bh*S + ii)*D + ln*4;
        if (half == 0) { atomicAdd(o,     x); atomicAdd(o + 1, y); }
        else           { atomicAdd(o + 2, z); atomicAdd(o + 3, u); }
    }
}

// ---------------------------------------------------------------------------
extern "C" void kernel_launch(void* const* d_in, const int* in_sizes, int n_in,
                              void* d_out, int out_size)
{
    const float* q   = (const float*)d_in[0];
    const float* k   = (const float*)d_in[1];
    const float* v   = (const float*)d_in[2];
    const int*   bm  = (const int*)  d_in[3];
    const float* rpb = (const float*)d_in[4];
    const float* W1  = (const float*)d_in[5];
    const float* A1  = (const float*)d_in[6];
    const float* W2  = (const float*)d_in[7];
    const float* A2  = (const float*)d_in[8];
    (void)in_sizes; (void)n_in; (void)out_size;   // mask (d_in[9]) is all-True

    cudaFuncSetAttribute(k_scores, cudaFuncAttributeMaxDynamicSharedMemorySize,
                         SMEM_SC);

    k_mixw  <<<128, 256>>>(W1, A1, W2, A2, (float4*)d_out);
    k_proj  <<<2*NC*BH*(S/K2_ROWS), 256>>>(q, v);
    k_scores<<<dim3(S/ITILE, BH), 256, SMEM_SC>>>(k, bm, rpb);
    k_out   <<<dim3((S/I2)*JSPLIT, BH), 256>>>(bm, (float*)d_out);
}